// round 5
// baseline (speedup 1.0000x reference)
#include <cuda_runtime.h>

#define T_STEPS 1000
#define BATCH   4096
#define IN_SZ   8
#define HID     50
#define OUT_SZ  6
#define GB      4             // batch elements per block
#define TPB_B   56            // threads per batch element: 28 row-pairs x 2 k-halves
#define NT      (GB * TPB_B)  // 224 threads = 7 warps
#define KHALF   28            // k-floats per half
#define RPAD    72            // r row stride: 16B aligned, +8 banks per batch slot
#define DT_F    0.1f

typedef unsigned long long ull;

__device__ __forceinline__ ull pack2(float lo, float hi) {
    ull u; asm("mov.b64 %0, {%1, %2};" : "=l"(u) : "f"(lo), "f"(hi)); return u;
}
__device__ __forceinline__ void unpack2(ull u, float& lo, float& hi) {
    asm("mov.b64 {%0, %1}, %2;" : "=f"(lo), "=f"(hi) : "l"(u));
}
#define FMA2(acc, a, b) asm("fma.rn.f32x2 %0, %1, %2, %0;" : "+l"(acc) : "l"(a), "l"(b))
#define ADD2(d, a, b)   asm("add.rn.f32x2 %0, %1, %2;" : "=l"(d) : "l"(a), "l"(b))

__global__ void __launch_bounds__(NT, 3) biornn_kernel(
    const float* __restrict__ x,      // (T, B, 8)
    const float* __restrict__ Win,    // (50, 8)
    const float* __restrict__ Wrec,   // (50, 50)
    const float* __restrict__ bias,   // (50,)
    const float* __restrict__ Wow,    // (6, 50)
    const float* __restrict__ Wob,    // (6,)
    float* __restrict__ out)          // (T, B, 6)
{
    __shared__ __align__(16) float r_s[2][GB][RPAD];

    const int tid  = threadIdx.x;
    const int bl   = tid / TPB_B;        // local batch 0..3
    const int r5   = tid - bl * TPB_B;   // 0..55
    const int half = r5 & 1;             // k-half
    const int jp   = r5 >> 1;            // row-pair 0..27
    const int row0 = jp;                 // always hidden
    const int row1 = jp + 28;            // hidden if <50, else output row
    const int b    = blockIdx.x * GB + bl;

    const int  myrow        = half ? row1 : row0;
    const bool hidden_owner = (myrow < HID);
    const bool out_owner    = !hidden_owner;   // implies half==1, row1 in [50,56)

    // zero shared (padding words 50..71 stay 0 forever)
    for (int i = tid; i < 2 * GB * RPAD; i += NT) ((float*)r_s)[i] = 0.f;

    // ---- weights into registers, packed f32x2, rows {row0,row1}, this k-half ----
    ull w0[KHALF / 2], w1[KHALF / 2];    // 14 + 14 pairs
    ull wi0[2], wi1[2];
    ull bj0p, bj1p;
    {
        const int kbase = half * KHALF;
        const float* rA = Wrec + row0 * HID;
        const float* rB = (row1 < HID) ? (Wrec + row1 * HID) : (Wow + (row1 - HID) * HID);
#pragma unroll
        for (int i = 0; i < KHALF / 2; i++) {
            const int k0 = kbase + 2 * i, k1 = k0 + 1;
            const float a0 = (k0 < HID) ? rA[k0] : 0.f;
            const float a1 = (k1 < HID) ? rA[k1] : 0.f;
            const float c0 = (k0 < HID) ? rB[k0] : 0.f;
            const float c1 = (k1 < HID) ? rB[k1] : 0.f;
            w0[i] = pack2(a0, a1);
            w1[i] = pack2(c0, c1);
        }
        const float* wiA = Win + row0 * IN_SZ + half * 4;
        wi0[0] = pack2(wiA[0], wiA[1]);
        wi0[1] = pack2(wiA[2], wiA[3]);
        if (row1 < HID) {
            const float* wiB = Win + row1 * IN_SZ + half * 4;
            wi1[0] = pack2(wiB[0], wiB[1]);
            wi1[1] = pack2(wiB[2], wiB[3]);
        } else {
            wi1[0] = 0ULL; wi1[1] = 0ULL;
        }
        if (half == 0) {   // bias injected once via half-0 acc init
            bj0p = pack2(bias[row0], 0.f);
            bj1p = pack2((row1 < HID) ? bias[row1] : Wob[row1 - HID], 0.f);
        } else {
            bj0p = 0ULL; bj1p = 0ULL;
        }
    }

    float h = 0.f;
    const ulonglong2* xp = reinterpret_cast<const ulonglong2*>(
        x + (size_t)b * IN_SZ + half * 4);
    const size_t XS = (size_t)BATCH * IN_SZ / 4;           // 8192 ulonglong2 / step
    float* op = out + (out_owner ? ((size_t)b * OUT_SZ + (myrow - HID)) : 0);

    ulonglong2 xc = *xp;  xp += XS;                        // prefetch x_0

    __syncthreads();

    int buf = 0;
#pragma unroll 1
    for (int t = 0; t < T_STEPS; t++) {
        if (hidden_owner) r_s[buf][bl][myrow] = fmaxf(h, 0.f);

        // prefetch x_{t+1} (clamped on last iter)
        const ulonglong2* pfp = (t < T_STEPS - 1) ? xp : (xp - XS);
        const ulonglong2 xn = *pfp;
        xp += XS;

        __syncthreads();

        ull a0 = bj0p, a0b = 0ULL, a1 = bj1p, a1b = 0ULL;
        FMA2(a0,  wi0[0], xc.x);  FMA2(a0b, wi0[1], xc.y);
        FMA2(a1,  wi1[0], xc.x);  FMA2(a1b, wi1[1], xc.y);

        const ulonglong2* rp = reinterpret_cast<const ulonglong2*>(
            &r_s[buf][bl][half * KHALF]);
#pragma unroll
        for (int kk = 0; kk < KHALF / 4; kk++) {     // 7 x LDS.128 -> 28 FMA2
            const ulonglong2 r2 = rp[kk];
            FMA2(a0,  w0[2 * kk],     r2.x);  FMA2(a0b, w0[2 * kk + 1], r2.y);
            FMA2(a1,  w1[2 * kk],     r2.x);  FMA2(a1b, w1[2 * kk + 1], r2.y);
        }

        ADD2(a0, a0, a0b);  ADD2(a1, a1, a1b);
        float s0l, s0h, s1l, s1h;
        unpack2(a0, s0l, s0h);  unpack2(a1, s1l, s1h);
        float s0 = s0l + s0h, s1 = s1l + s1h;
        s0 += __shfl_xor_sync(0xffffffffu, s0, 1);   // combine k-halves, row0
        s1 += __shfl_xor_sync(0xffffffffu, s1, 1);   // combine k-halves, row1

        if (hidden_owner) {
            const float ms = half ? s1 : s0;
            h = fmaf(DT_F, ms - h, h);               // h += DT*(acc - h)
        } else {
            *op = s1;
        }
        if (out_owner) op += BATCH * OUT_SZ;

        xc = xn;
        buf ^= 1;
    }
}

extern "C" void kernel_launch(void* const* d_in, const int* in_sizes, int n_in,
                              void* d_out, int out_size) {
    const float* x    = (const float*)d_in[0];
    const float* Win  = (const float*)d_in[1];
    const float* Wrec = (const float*)d_in[2];
    const float* bias = (const float*)d_in[3];
    const float* Wow  = (const float*)d_in[4];
    const float* Wob  = (const float*)d_in[5];
    float* out = (float*)d_out;

    biornn_kernel<<<BATCH / GB, NT>>>(x, Win, Wrec, bias, Wow, Wob, out);
}

// round 6
// speedup vs baseline: 1.0924x; 1.0924x over previous
#include <cuda_runtime.h>

#define T_STEPS 1000
#define BATCH   4096
#define IN_SZ   8
#define HID     50
#define OUT_SZ  6
#define NT      64            // 32 row-pairs x 2 k-halves; one batch element per block
#define KHALF   28            // k-floats per half
#define RW      64            // r buffer width (words 50..63 stay 0)
#define DT_F    0.1f

typedef unsigned long long ull;

__device__ __forceinline__ ull pack2(float lo, float hi) {
    ull u; asm("mov.b64 %0, {%1, %2};" : "=l"(u) : "f"(lo), "f"(hi)); return u;
}
__device__ __forceinline__ void unpack2(ull u, float& lo, float& hi) {
    asm("mov.b64 {%0, %1}, %2;" : "=f"(lo), "=f"(hi) : "l"(u));
}
#define FMA2(acc, a, b) asm("fma.rn.f32x2 %0, %1, %2, %0;" : "+l"(acc) : "l"(a), "l"(b))
#define ADD2(d, a, b)   asm("add.rn.f32x2 %0, %1, %2;" : "=l"(d) : "l"(a), "l"(b))

__global__ void __launch_bounds__(NT, 11) biornn_kernel(
    const float* __restrict__ x,      // (T, B, 8)
    const float* __restrict__ Win,    // (50, 8)
    const float* __restrict__ Wrec,   // (50, 50)
    const float* __restrict__ bias,   // (50,)
    const float* __restrict__ Wow,    // (6, 50)
    const float* __restrict__ Wob,    // (6,)
    float* __restrict__ out)          // (T, B, 6)
{
    __shared__ __align__(16) float r_s[2][RW];

    const int tid  = threadIdx.x;
    const int half = tid & 1;            // k-half: 0 -> k [0,28), 1 -> k [28,56)
    const int jp   = tid >> 1;           // row-pair 0..31
    const int row0 = jp;                 // 0..31, always hidden
    const int row1 = jp + 32;            // 32..49 hidden, 50..55 output, 56..63 dead
    const int b    = blockIdx.x;

    const int  myrow        = half ? row1 : row0;
    const bool hidden_owner = (myrow < HID);
    const bool out_owner    = (myrow >= HID) && (myrow < HID + OUT_SZ);

    // zero shared (words 50..63 stay 0 forever; dead rows never published)
    for (int i = tid; i < 2 * RW; i += NT) ((float*)r_s)[i] = 0.f;

    // ---- weights into registers, packed f32x2, rows {row0,row1}, this k-half ----
    ull w0[KHALF / 2], w1[KHALF / 2];    // 14 + 14 pairs
    ull wi0[2], wi1[2];
    ull bj0p, bj1p;
    {
        const int kbase = half * KHALF;
        const bool r1h = (row1 < HID);                 // row1 is hidden
        const bool r1o = out_owner || (half == 0 && row1 >= HID && row1 < HID + OUT_SZ);
        const float* rA = Wrec + row0 * HID;
        const float* rB = r1h ? (Wrec + row1 * HID)
                              : ((row1 < HID + OUT_SZ) ? (Wow + (row1 - HID) * HID) : Wrec);
        const bool r1live = (row1 < HID + OUT_SZ);
#pragma unroll
        for (int i = 0; i < KHALF / 2; i++) {
            const int k0 = kbase + 2 * i, k1 = k0 + 1;
            const float a0 = (k0 < HID) ? rA[k0] : 0.f;
            const float a1 = (k1 < HID) ? rA[k1] : 0.f;
            const float c0 = (r1live && k0 < HID) ? rB[k0] : 0.f;
            const float c1 = (r1live && k1 < HID) ? rB[k1] : 0.f;
            w0[i] = pack2(a0, a1);
            w1[i] = pack2(c0, c1);
        }
        const float* wiA = Win + row0 * IN_SZ + half * 4;
        wi0[0] = pack2(wiA[0], wiA[1]);
        wi0[1] = pack2(wiA[2], wiA[3]);
        if (r1h) {
            const float* wiB = Win + row1 * IN_SZ + half * 4;
            wi1[0] = pack2(wiB[0], wiB[1]);
            wi1[1] = pack2(wiB[2], wiB[3]);
        } else {
            wi1[0] = 0ULL; wi1[1] = 0ULL;
        }
        if (half == 0) {   // bias/out-bias injected once via half-0 acc init
            bj0p = pack2(bias[row0], 0.f);
            float b1 = 0.f;
            if (r1h) b1 = bias[row1];
            else if (row1 < HID + OUT_SZ) b1 = Wob[row1 - HID];
            bj1p = pack2(b1, 0.f);
        } else {
            bj0p = 0ULL; bj1p = 0ULL;
        }
        (void)r1o;
    }

    float h = 0.f;
    const ulonglong2* xp = reinterpret_cast<const ulonglong2*>(
        x + (size_t)b * IN_SZ + half * 4);
    const size_t XS = (size_t)BATCH * IN_SZ / 4;           // 8192 ulonglong2 / step
    float* op = out + (out_owner ? ((size_t)b * OUT_SZ + (myrow - HID)) : 0);

    // precomputed LDS base pointers for both buffers (select per step)
    const ulonglong2* const rp0 =
        reinterpret_cast<const ulonglong2*>(&r_s[0][half * KHALF]);
    const ulonglong2* const rp1 =
        reinterpret_cast<const ulonglong2*>(&r_s[1][half * KHALF]);

    ulonglong2 xc = *xp;  xp += XS;                        // prefetch x_0

    __syncthreads();

    int buf = 0;
#pragma unroll 1
    for (int t = 0; t < T_STEPS; t++) {
        if (hidden_owner) r_s[buf][myrow] = fmaxf(h, 0.f);

        // prefetch x_{t+1} (clamped on last iter)
        const ulonglong2* pfp = (t < T_STEPS - 1) ? xp : (xp - XS);
        const ulonglong2 xn = *pfp;
        xp += XS;

        __syncthreads();

        ull a0 = bj0p, a0b = 0ULL, a1 = bj1p, a1b = 0ULL;
        FMA2(a0,  wi0[0], xc.x);  FMA2(a0b, wi0[1], xc.y);
        FMA2(a1,  wi1[0], xc.x);  FMA2(a1b, wi1[1], xc.y);

        const ulonglong2* rp = buf ? rp1 : rp0;
#pragma unroll
        for (int kk = 0; kk < KHALF / 4; kk++) {     // 7 x LDS.128 -> 28 FMA2
            const ulonglong2 r2 = rp[kk];
            FMA2(a0,  w0[2 * kk],     r2.x);  FMA2(a0b, w0[2 * kk + 1], r2.y);
            FMA2(a1,  w1[2 * kk],     r2.x);  FMA2(a1b, w1[2 * kk + 1], r2.y);
        }

        ADD2(a0, a0, a0b);  ADD2(a1, a1, a1b);
        float s0l, s0h, s1l, s1h;
        unpack2(a0, s0l, s0h);  unpack2(a1, s1l, s1h);
        float s0 = s0l + s0h, s1 = s1l + s1h;
        s0 += __shfl_xor_sync(0xffffffffu, s0, 1);   // combine k-halves, row0
        s1 += __shfl_xor_sync(0xffffffffu, s1, 1);   // combine k-halves, row1

        if (hidden_owner) {
            const float ms = half ? s1 : s0;
            h = fmaf(DT_F, ms - h, h);               // h += DT*(acc - h)
        } else if (out_owner) {
            *op = s1;
        }
        if (out_owner) op += BATCH * OUT_SZ;

        xc = xn;
        buf ^= 1;
    }
}

extern "C" void kernel_launch(void* const* d_in, const int* in_sizes, int n_in,
                              void* d_out, int out_size) {
    const float* x    = (const float*)d_in[0];
    const float* Win  = (const float*)d_in[1];
    const float* Wrec = (const float*)d_in[2];
    const float* bias = (const float*)d_in[3];
    const float* Wow  = (const float*)d_in[4];
    const float* Wob  = (const float*)d_in[5];
    float* out = (float*)d_out;

    biornn_kernel<<<BATCH, NT>>>(x, Win, Wrec, bias, Wow, Wob, out);
}